// round 15
// baseline (speedup 1.0000x reference)
#include <cuda_runtime.h>
#include <cuda_bf16.h>
#include <cuda_fp16.h>
#include <stdint.h>
#include <math.h>

typedef __half HALF;

// ---------------- dimensions ----------------
#define S   2048
#define D   2048
#define H   16
#define HD  128
#define FF  8192
#define VOC 32000
#define LN_EPS 1e-5f
#define SD  (S * D)
#define DD  (D * D)

// ---------------- scratch ----------------
__device__ float g_x  [SD];
__device__ float g_x2 [SD];
__device__ float g_x3 [SD];

__device__ HALF g_hh [SD];
__device__ HALF g_h2h[SD];
__device__ HALF g_hfh[SD];
__device__ HALF g_aoh[SD];
__device__ HALF g_ffh[S * FF];
__device__ HALF g_qkvh[3 * SD];       // q,k,v fp16 hi
__device__ HALF g_vth[SD];            // V^T fp16 [H][HD][S]

__device__ HALF g_wqkvTh[3 * DD];
__device__ HALF g_woTh[DD];
__device__ HALF g_wfiTh[D * FF];
__device__ HALF g_wfoTh[D * FF];
__device__ HALF g_woutTh[(size_t)D * VOC];

__device__ int g_tok64;

// ---------------- PTX helpers (plain sm_103-legal) ----------------
__device__ __forceinline__ uint32_t smem_u32(const void* p) {
    uint32_t a;
    asm("{ .reg .u64 t; cvta.to.shared.u64 t, %1; cvt.u32.u64 %0, t; }" : "=r"(a) : "l"(p));
    return a;
}
__device__ __forceinline__ void ldm_x4(uint32_t* r, uint32_t addr) {
    asm volatile("ldmatrix.sync.aligned.m8n8.x4.shared.b16 {%0,%1,%2,%3}, [%4];"
                 : "=r"(r[0]), "=r"(r[1]), "=r"(r[2]), "=r"(r[3]) : "r"(addr));
}
__device__ __forceinline__ void mma_fp16(float* c, const uint32_t* a, const uint32_t* b) {
    asm volatile(
        "mma.sync.aligned.m16n8k16.row.col.f32.f16.f16.f32 "
        "{%0,%1,%2,%3}, {%4,%5,%6,%7}, {%8,%9}, {%0,%1,%2,%3};"
        : "+f"(c[0]), "+f"(c[1]), "+f"(c[2]), "+f"(c[3])
        : "r"(a[0]), "r"(a[1]), "r"(a[2]), "r"(a[3]), "r"(b[0]), "r"(b[1]));
}
#define CP16(dst, src) \
    asm volatile("cp.async.cg.shared.global [%0], [%1], 16;" :: "r"(dst), "l"(src) : "memory")
#define CPCOMMIT() asm volatile("cp.async.commit_group;" ::: "memory")
#define CPWAIT0() asm volatile("cp.async.wait_group 0;" ::: "memory")
#define CPWAIT1() asm volatile("cp.async.wait_group 1;" ::: "memory")

#define SW64(o) ((o) ^ (((o) >> 3) & 0x30))

__device__ __forceinline__ uint32_t pack2h(float a, float b)
{
    __half2 h2 = __halves2half2(__float2half_rn(a), __float2half_rn(b));
    return *reinterpret_cast<uint32_t*>(&h2);
}

// ---------------- token detect + embed ----------------
__global__ void detect_tok_kernel(const int* __restrict__ t)
{
    __shared__ int any;
    if (threadIdx.x == 0) any = 0;
    __syncthreads();
    int local = 0;
    for (int i = threadIdx.x; i < S / 2; i += blockDim.x)
        if (t[2 * i + 1] != 0) local = 1;
    if (local) any = 1;
    __syncthreads();
    if (threadIdx.x == 0) g_tok64 = (any == 0) ? 1 : 0;
}

__global__ void embed_kernel(const int* __restrict__ tok,
                             const float* __restrict__ te,
                             const float* __restrict__ pe,
                             float* __restrict__ x)
{
    const int s = blockIdx.x;
    const int t = g_tok64 ? tok[2 * s] : tok[s];
    const float4* e = (const float4*)(te + (size_t)t * D);
    const float4* p = (const float4*)(pe + (size_t)s * D);
    float4*       o = (float4*)(x + (size_t)s * D);
    for (int i = threadIdx.x; i < D / 4; i += blockDim.x) {
        float4 a = e[i], b = p[i];
        o[i] = make_float4(a.x + b.x, a.y + b.y, a.z + b.z, a.w + b.w);
    }
}

// ---------------- weight convert + transpose: fp32 [K][N] -> fp16 hi [N][K] ----------------
__global__ void convT_kernel(const float* __restrict__ src, int K, int N,
                             HALF* __restrict__ dhi)
{
    __shared__ float t[32][33];
    const int n0 = blockIdx.x * 32, k0 = blockIdx.y * 32;
    const int tx = threadIdx.x & 31, ty = threadIdx.x >> 5;
#pragma unroll
    for (int r = 0; r < 4; r++)
        t[ty + 8 * r][tx] = src[(size_t)(k0 + ty + 8 * r) * N + n0 + tx];
    __syncthreads();
#pragma unroll
    for (int r = 0; r < 4; r++) {
        const int n = n0 + ty + 8 * r, k = k0 + tx;
        dhi[(size_t)n * K + k] = __float2half_rn(t[tx][ty + 8 * r]);
    }
}

// ---------------- V transpose: fp16 [S][D] head slice -> fp16 [H][HD][S] ----------------
__global__ void vtrans_kernel(const HALF* __restrict__ vh, HALF* __restrict__ vth)
{
    __shared__ HALF th[32][33];
    const int h = blockIdx.z;
    const int d0 = blockIdx.x * 32, s0 = blockIdx.y * 32;
    const int tx = threadIdx.x & 31, ty = threadIdx.x >> 5;
#pragma unroll
    for (int r = 0; r < 4; r++) {
        const size_t src = (size_t)(s0 + ty + 8 * r) * D + h * HD + d0 + tx;
        th[ty + 8 * r][tx] = vh[src];
    }
    __syncthreads();
#pragma unroll
    for (int r = 0; r < 4; r++) {
        const size_t dst = ((size_t)h * HD + d0 + ty + 8 * r) * S + s0 + tx;
        vth[dst] = th[tx][ty + 8 * r];
    }
}

// ---------------- layernorm: fp32 in -> fp16 hi out ----------------
__global__ void ln_kernel(const float* __restrict__ x,
                          const float* __restrict__ g,
                          const float* __restrict__ b,
                          HALF* __restrict__ oh)
{
    __shared__ float r1[8], r2[8];
    __shared__ float s_mean, s_inv;
    const int s   = blockIdx.x;
    const int tid = threadIdx.x;
    const float4* xr = (const float4*)(x + (size_t)s * D);
    float4 v0 = xr[tid];
    float4 v1 = xr[tid + 256];
    float sum = v0.x + v0.y + v0.z + v0.w + v1.x + v1.y + v1.z + v1.w;
    float sq  = v0.x * v0.x + v0.y * v0.y + v0.z * v0.z + v0.w * v0.w
              + v1.x * v1.x + v1.y * v1.y + v1.z * v1.z + v1.w * v1.w;
#pragma unroll
    for (int o = 16; o; o >>= 1) {
        sum += __shfl_xor_sync(0xffffffffu, sum, o);
        sq  += __shfl_xor_sync(0xffffffffu, sq,  o);
    }
    const int w = tid >> 5;
    if ((tid & 31) == 0) { r1[w] = sum; r2[w] = sq; }
    __syncthreads();
    if (tid == 0) {
        float ts = 0.f, tq = 0.f;
#pragma unroll
        for (int i = 0; i < 8; i++) { ts += r1[i]; tq += r2[i]; }
        const float mean = ts / (float)D;
        const float var  = tq / (float)D - mean * mean;
        s_mean = mean;
        s_inv  = rsqrtf(var + LN_EPS);
    }
    __syncthreads();
    const float mean = s_mean, inv = s_inv;
    const float4* gg = (const float4*)g;
    const float4* bb = (const float4*)b;
    float4 g0 = gg[tid], g1 = gg[tid + 256];
    float4 b0 = bb[tid], b1 = bb[tid + 256];
    float o00 = (v0.x - mean) * inv * g0.x + b0.x;
    float o01 = (v0.y - mean) * inv * g0.y + b0.y;
    float o02 = (v0.z - mean) * inv * g0.z + b0.z;
    float o03 = (v0.w - mean) * inv * g0.w + b0.w;
    float o10 = (v1.x - mean) * inv * g1.x + b1.x;
    float o11 = (v1.y - mean) * inv * g1.y + b1.y;
    float o12 = (v1.z - mean) * inv * g1.z + b1.z;
    float o13 = (v1.w - mean) * inv * g1.w + b1.w;
    const size_t e0 = (size_t)s * D + tid * 4;
    *(uint2*)(oh + e0)        = make_uint2(pack2h(o00, o01), pack2h(o02, o03));
    *(uint2*)(oh + e0 + 1024) = make_uint2(pack2h(o10, o11), pack2h(o12, o13));
}

// ---------------- fused flash attention (unchanged from R11) ----------------
#define FLASH_STAGE 65536
#define FLASH_SMEM  (3 * FLASH_STAGE)

__global__ void __launch_bounds__(256, 1)
flash_kernel(const HALF* __restrict__ q, const HALF* __restrict__ k,
             const HALF* __restrict__ vt, HALF* __restrict__ out, float alpha)
{
    extern __shared__ char smem[];
    const uint32_t sb = smem_u32(smem);
    const int tid = threadIdx.x, wid = tid >> 5, lane = tid & 31;
    const int q0 = blockIdx.x * 128;
    const int h  = blockIdx.y;

    const int rowL = tid >> 1;
    const int half = tid & 1;
    uint32_t so[2][4];
#pragma unroll
    for (int c = 0; c < 2; c++)
#pragma unroll
        for (int u = 0; u < 4; u++)
            so[c][u] = c * 16384 + SW64((uint32_t)(rowL * 128 + half * 64 + u * 16));
    const int gofs = half * 32;

    const int a_row = lane & 15;
    const int a_kc  = (lane >> 4) * 8;
    const int b_row = (lane & 7) + (lane >> 4) * 8;
    const int b_kc  = ((lane >> 3) & 1) * 8;

    {
        const HALF* qp = q + (size_t)(q0 + rowL) * D + h * HD + gofs;
#pragma unroll
        for (int c = 0; c < 2; c++)
#pragma unroll
            for (int u = 0; u < 4; u++)
                CP16(sb + so[c][u], qp + c * 64 + u * 8);
        CPCOMMIT(); CPWAIT0();
    }
    __syncthreads();
    uint32_t qf[8][4];
    {
        const int wq = wid * 16;
#pragma unroll
        for (int j = 0; j < 8; j++) {
            const int kcol = j * 16 + a_kc;
            ldm_x4(qf[j], sb + (kcol >> 6) * 16384
                             + SW64((uint32_t)((wq + a_row) * 128 + (kcol & 63) * 2)));
        }
    }
    __syncthreads();

    const HALF* kbase = k + (size_t)rowL * D + h * HD + gofs;
    const HALF* vbase = vt + ((size_t)h * HD + rowL) * S + gofs;

    auto issue = [&](int t, int st) {
        const uint32_t sB = sb + st * FLASH_STAGE;
        const HALF* kp = kbase + (size_t)(t * 128) * D;
        const HALF* vp = vbase + t * 128;
#pragma unroll
        for (int c = 0; c < 2; c++)
#pragma unroll
            for (int u = 0; u < 4; u++) {
                CP16(sB + so[c][u],         kp + c * 64 + u * 8);
                CP16(sB + 32768 + so[c][u], vp + c * 64 + u * 8);
            }
        CPCOMMIT();
    };

    float oa[16][4];
#pragma unroll
    for (int i = 0; i < 16; i++)
#pragma unroll
        for (int j = 0; j < 4; j++) oa[i][j] = 0.f;
    float m0 = -1e30f, m1 = -1e30f, l0 = 0.f, l1 = 0.f;

    issue(0, 0);
    issue(1, 1);

    for (int t = 0; t < 16; t++) {
        if (t + 1 < 16) { CPWAIT1(); } else { CPWAIT0(); }
        __syncthreads();
        if (t + 2 < 16) issue(t + 2, (t + 2) % 3);

        const uint32_t stK = sb + (t % 3) * FLASH_STAGE;
        const uint32_t stV = stK + 32768;

        float s[16][4];
#pragma unroll
        for (int i = 0; i < 16; i++)
#pragma unroll
            for (int j = 0; j < 4; j++) s[i][j] = 0.f;
#pragma unroll
        for (int j = 0; j < 8; j++) {
            const int kcol = j * 16 + b_kc;
            const uint32_t kadd = stK + (kcol >> 6) * 16384;
            const uint32_t kc2 = (kcol & 63) * 2;
#pragma unroll
            for (int nt2 = 0; nt2 < 8; nt2++) {
                uint32_t bh[4];
                ldm_x4(bh, kadd + SW64((uint32_t)((nt2 * 16 + b_row) * 128) + kc2));
                mma_fp16(s[2 * nt2],     qf[j], bh);
                mma_fp16(s[2 * nt2 + 1], qf[j], bh + 2);
            }
        }

        float tm0 = -1e30f, tm1 = -1e30f;
#pragma unroll
        for (int nt = 0; nt < 16; nt++) {
            s[nt][0] *= alpha; s[nt][1] *= alpha;
            s[nt][2] *= alpha; s[nt][3] *= alpha;
            tm0 = fmaxf(tm0, fmaxf(s[nt][0], s[nt][1]));
            tm1 = fmaxf(tm1, fmaxf(s[nt][2], s[nt][3]));
        }
        tm0 = fmaxf(tm0, __shfl_xor_sync(0xffffffffu, tm0, 1));
        tm0 = fmaxf(tm0, __shfl_xor_sync(0xffffffffu, tm0, 2));
        tm1 = fmaxf(tm1, __shfl_xor_sync(0xffffffffu, tm1, 1));
        tm1 = fmaxf(tm1, __shfl_xor_sync(0xffffffffu, tm1, 2));
        const float nm0 = fmaxf(m0, tm0), nm1 = fmaxf(m1, tm1);
        const float f0 = __expf(m0 - nm0), f1 = __expf(m1 - nm1);
        m0 = nm0; m1 = nm1;
        float ps0 = 0.f, ps1 = 0.f;
#pragma unroll
        for (int nt = 0; nt < 16; nt++) {
            s[nt][0] = __expf(s[nt][0] - nm0); ps0 += s[nt][0];
            s[nt][1] = __expf(s[nt][1] - nm0); ps0 += s[nt][1];
            s[nt][2] = __expf(s[nt][2] - nm1); ps1 += s[nt][2];
            s[nt][3] = __expf(s[nt][3] - nm1); ps1 += s[nt][3];
        }
        ps0 += __shfl_xor_sync(0xffffffffu, ps0, 1);
        ps0 += __shfl_xor_sync(0xffffffffu, ps0, 2);
        ps1 += __shfl_xor_sync(0xffffffffu, ps1, 1);
        ps1 += __shfl_xor_sync(0xffffffffu, ps1, 2);
        l0 = l0 * f0 + ps0;
        l1 = l1 * f1 + ps1;
#pragma unroll
        for (int vtt = 0; vtt < 16; vtt++) {
            oa[vtt][0] *= f0; oa[vtt][1] *= f0;
            oa[vtt][2] *= f1; oa[vtt][3] *= f1;
        }

#pragma unroll
        for (int ks = 0; ks < 8; ks++) {
            uint32_t af[4];
            af[0] = pack2h(s[2 * ks][0],     s[2 * ks][1]);
            af[1] = pack2h(s[2 * ks][2],     s[2 * ks][3]);
            af[2] = pack2h(s[2 * ks + 1][0], s[2 * ks + 1][1]);
            af[3] = pack2h(s[2 * ks + 1][2], s[2 * ks + 1][3]);
            const int scol = ks * 16 + b_kc;
            const uint32_t vadd = stV + (scol >> 6) * 16384;
            const uint32_t sc2 = (scol & 63) * 2;
#pragma unroll
            for (int vt2 = 0; vt2 < 8; vt2++) {
                uint32_t bh[4];
                ldm_x4(bh, vadd + SW64((uint32_t)((vt2 * 16 + b_row) * 128) + sc2));
                mma_fp16(oa[2 * vt2],     af, bh);
                mma_fp16(oa[2 * vt2 + 1], af, bh + 2);
            }
        }
    }

    const float i0 = 1.f / l0, i1 = 1.f / l1;
    const int r0 = q0 + wid * 16 + (lane >> 2);
    HALF* op0 = out + (size_t)r0 * D + h * HD + (lane & 3) * 2;
    HALF* op1 = op0 + (size_t)8 * D;
#pragma unroll
    for (int vtt = 0; vtt < 16; vtt++) {
        *(uint32_t*)(op0 + vtt * 8) = pack2h(oa[vtt][0] * i0, oa[vtt][1] * i0);
        *(uint32_t*)(op1 + vtt * 8) = pack2h(oa[vtt][2] * i1, oa[vtt][3] * i1);
    }
}

// ---------------- cp.async pipelined GEMM (fp16, 1-pass, BK=64) ----------------
// Stage: A blocks [k0-31]@+0, [k32-63]@+8192; B blocks @+16384, +24576.
// Inner loop: all 4 B-frags of a ks-step prefetched back-to-back (MLP=4),
// A-frags for ks+1 hoisted ahead of the mma burst.
#define OUT_F32       0
#define OUT_F32RES    1
#define OUT_RELU_HI   4
#define OUT_HI        5

#define GSTAGE 32768
#define GEMM_SMEM (3 * GSTAGE)

template <int OUT>
__global__ void __launch_bounds__(256, 2)
tc_gemm(const uint16_t* __restrict__ Ah, int lda, long long sA,
        const uint16_t* __restrict__ Bh, int ldb, long long sB,
        const float* __restrict__ Res,
        float* __restrict__ Cf, uint16_t* __restrict__ Chi,
        int ldc, long long sC, int K, float alpha)
{
    extern __shared__ char smem[];
    const uint32_t sb = smem_u32(smem);
    const int tid = threadIdx.x, wid = tid >> 5, lane = tid & 31;
    const int z = blockIdx.z;
    Ah += (size_t)z * sA;
    Bh += (size_t)z * sB;
    const int m0 = blockIdx.x * 128;   // M fast-varying
    const int n0 = blockIdx.y * 128;
    const int wm = (wid & 3) * 32;
    const int wn = (wid >> 2) * 64;

    // loader (512B/warp window, conflict-free + coalesced)
    const int rowL = tid >> 2;
    const int cL   = tid & 3;
    const uint32_t o0 = SW64((uint32_t)(rowL * 64 + cL * 16));
    const uint32_t o1 = SW64((uint32_t)((rowL + 64) * 64 + cL * 16));
    const uint16_t* aht = Ah + (size_t)(m0 + rowL) * lda + cL * 8;
    const uint16_t* bht = Bh + (size_t)(n0 + rowL) * ldb + cL * 8;
    const size_t a64 = (size_t)64 * lda;
    const size_t b64 = (size_t)64 * ldb;

    auto issue = [&](int idx, int s) {
        const uint32_t st = sb + s * GSTAGE;
        const uint16_t* a1 = aht + idx * 64;
        const uint16_t* b1 = bht + idx * 64;
        CP16(st + o0,          a1);
        CP16(st + o1,          a1 + a64);
        CP16(st + 8192 + o0,   a1 + 32);
        CP16(st + 8192 + o1,   a1 + 32 + a64);
        CP16(st + 16384 + o0,  b1);
        CP16(st + 16384 + o1,  b1 + b64);
        CP16(st + 24576 + o0,  b1 + 32);
        CP16(st + 24576 + o1,  b1 + 32 + b64);
        CPCOMMIT();
    };

    float acc[2][8][4];
#pragma unroll
    for (int i = 0; i < 2; i++)
#pragma unroll
        for (int j = 0; j < 8; j++)
#pragma unroll
            for (int q = 0; q < 4; q++) acc[i][j][q] = 0.f;

    const int a_row = lane & 15;
    const int a_kc  = (lane >> 4) * 8;
    const int b_row = (lane & 7) + (lane >> 4) * 8;
    const int b_kc  = ((lane >> 3) & 1) * 8;

    // precomputed per-warp frag addresses (stage-relative)
    uint32_t aofs[4][2], bofs[4][4];
#pragma unroll
    for (int ks = 0; ks < 4; ks++) {
        const uint32_t blk = (uint32_t)(ks >> 1) * 8192;
        const uint32_t akc2 = (uint32_t)(((ks & 1) * 16 + a_kc) * 2);
        const uint32_t bkc2 = (uint32_t)(((ks & 1) * 16 + b_kc) * 2);
#pragma unroll
        for (int mf = 0; mf < 2; mf++)
            aofs[ks][mf] = blk + SW64((uint32_t)((wm + mf * 16 + a_row) * 64) + akc2);
#pragma unroll
        for (int p = 0; p < 4; p++)
            bofs[ks][p] = 16384 + blk + SW64((uint32_t)((wn + p * 16 + b_row) * 64) + bkc2);
    }

    const int nch = K >> 6;
    issue(0, 0);
    if (nch > 1) issue(1, 1);

    for (int i = 0; i < nch; i++) {
        if (i + 1 < nch) { CPWAIT1(); } else { CPWAIT0(); }
        __syncthreads();                       // single barrier per chunk
        if (i + 2 < nch) issue(i + 2, (i + 2) % 3);

        const uint32_t st = sb + (i % 3) * GSTAGE;

        // prime ks=0 frags
        uint32_t ah[2][4], bh[4][4];
#pragma unroll
        for (int mf = 0; mf < 2; mf++) ldm_x4(ah[mf], st + aofs[0][mf]);
#pragma unroll
        for (int p = 0; p < 4; p++)    ldm_x4(bh[p],  st + bofs[0][p]);

#pragma unroll
        for (int ks = 0; ks < 4; ks++) {
            uint32_t ah2[2][4], bh2[4][4];
            if (ks < 3) {   // prefetch next ks-step while this one computes
#pragma unroll
                for (int mf = 0; mf < 2; mf++) ldm_x4(ah2[mf], st + aofs[ks + 1][mf]);
#pragma unroll
                for (int p = 0; p < 4; p++)    ldm_x4(bh2[p],  st + bofs[ks + 1][p]);
            }
#pragma unroll
            for (int p = 0; p < 4; p++) {
#pragma unroll
                for (int mf = 0; mf < 2; mf++) {
                    mma_fp16(acc[mf][2 * p],     ah[mf], bh[p]);
                    mma_fp16(acc[mf][2 * p + 1], ah[mf], bh[p] + 2);
                }
            }
            if (ks < 3) {
#pragma unroll
                for (int mf = 0; mf < 2; mf++)
#pragma unroll
                    for (int u = 0; u < 4; u++) ah[mf][u] = ah2[mf][u];
#pragma unroll
                for (int p = 0; p < 4; p++)
#pragma unroll
                    for (int u = 0; u < 4; u++) bh[p][u] = bh2[p][u];
            }
        }
    }

    const int r  = lane >> 2;
    const int c2 = (lane & 3) * 2;
#pragma unroll
    for (int mf = 0; mf < 2; mf++) {
#pragma unroll
        for (int hh = 0; hh < 2; hh++) {
            const int m = m0 + wm + mf * 16 + r + 8 * hh;
            const size_t rofs = (size_t)z * sC + (size_t)m * ldc + n0 + wn;
#pragma unroll
            for (int nf = 0; nf < 8; nf++) {
                float x0 = acc[mf][nf][2 * hh]     * alpha;
                float x1 = acc[mf][nf][2 * hh + 1] * alpha;
                const int nn = nf * 8 + c2;
                if (OUT == OUT_F32RES) {
                    const float2 rr = *(const float2*)(Res + (size_t)m * ldc + n0 + wn + nn);
                    x0 += rr.x; x1 += rr.y;
                } else if (OUT == OUT_RELU_HI) {
                    x0 = fmaxf(x0, 0.f); x1 = fmaxf(x1, 0.f);
                }
                if (OUT == OUT_F32 || OUT == OUT_F32RES) {
                    *(float2*)(Cf + rofs + nn) = make_float2(x0, x1);
                } else {
                    *(uint32_t*)(Chi + rofs + nn) = pack2h(x0, x1);
                }
            }
        }
    }
}

// ---------------- launch ----------------
extern "C" void kernel_launch(void* const* d_in, const int* in_sizes, int n_in,
                              void* d_out, int out_size)
{
    const int*   tokens = (const int*)d_in[0];
    const float* temb   = (const float*)d_in[1];
    const float* pemb   = (const float*)d_in[2];
    const float* wq     = (const float*)d_in[3];
    const float* wk     = (const float*)d_in[4];
    const float* wv     = (const float*)d_in[5];
    const float* wo     = (const float*)d_in[6];
    const float* wfi    = (const float*)d_in[7];
    const float* wfo    = (const float*)d_in[8];
    const float* ln1g   = (const float*)d_in[9];
    const float* ln1b   = (const float*)d_in[10];
    const float* ln2g   = (const float*)d_in[11];
    const float* ln2b   = (const float*)d_in[12];
    const float* lnfg   = (const float*)d_in[13];
    const float* lnfb   = (const float*)d_in[14];
    const float* wout   = (const float*)d_in[15];
    float*       out    = (float*)d_out;

    float *px, *px2, *px3;
    HALF *phh, *ph2h, *phfh, *paoh, *pffh, *pvth, *pqkvh;
    HALF *pwqkvTh, *pwoTh, *pwfiTh, *pwfoTh, *pwoutTh;
    cudaGetSymbolAddress((void**)&px,   g_x);
    cudaGetSymbolAddress((void**)&px2,  g_x2);
    cudaGetSymbolAddress((void**)&px3,  g_x3);
    cudaGetSymbolAddress((void**)&phh,  g_hh);
    cudaGetSymbolAddress((void**)&ph2h, g_h2h);
    cudaGetSymbolAddress((void**)&phfh, g_hfh);
    cudaGetSymbolAddress((void**)&paoh, g_aoh);
    cudaGetSymbolAddress((void**)&pffh, g_ffh);
    cudaGetSymbolAddress((void**)&pvth, g_vth);
    cudaGetSymbolAddress((void**)&pqkvh, g_qkvh);
    cudaGetSymbolAddress((void**)&pwqkvTh, g_wqkvTh);
    cudaGetSymbolAddress((void**)&pwoTh, g_woTh);
    cudaGetSymbolAddress((void**)&pwfiTh, g_wfiTh);
    cudaGetSymbolAddress((void**)&pwfoTh, g_wfoTh);
    cudaGetSymbolAddress((void**)&pwoutTh, g_woutTh);

    cudaFuncSetAttribute(tc_gemm<OUT_HI>,
                         cudaFuncAttributeMaxDynamicSharedMemorySize, GEMM_SMEM);
    cudaFuncSetAttribute(tc_gemm<OUT_F32RES>,
                         cudaFuncAttributeMaxDynamicSharedMemorySize, GEMM_SMEM);
    cudaFuncSetAttribute(tc_gemm<OUT_RELU_HI>,
                         cudaFuncAttributeMaxDynamicSharedMemorySize, GEMM_SMEM);
    cudaFuncSetAttribute(tc_gemm<OUT_F32>,
                         cudaFuncAttributeMaxDynamicSharedMemorySize, GEMM_SMEM);
    cudaFuncSetAttribute(flash_kernel,
                         cudaFuncAttributeMaxDynamicSharedMemorySize, FLASH_SMEM);

    // ---- side stream for all weight conversions ----
    cudaStream_t s2;
    cudaStreamCreateWithFlags(&s2, cudaStreamNonBlocking);
    cudaEvent_t evFork, evWqkv, evWo, evWfi, evWfo, evWout;
    cudaEventCreateWithFlags(&evFork, cudaEventDisableTiming);
    cudaEventCreateWithFlags(&evWqkv, cudaEventDisableTiming);
    cudaEventCreateWithFlags(&evWo,   cudaEventDisableTiming);
    cudaEventCreateWithFlags(&evWfi,  cudaEventDisableTiming);
    cudaEventCreateWithFlags(&evWfo,  cudaEventDisableTiming);
    cudaEventCreateWithFlags(&evWout, cudaEventDisableTiming);

    detect_tok_kernel<<<1, 256>>>(tokens);
    cudaEventRecord(evFork, 0);
    cudaStreamWaitEvent(s2, evFork, 0);

    convT_kernel<<<dim3(D / 32, D / 32), 256, 0, s2>>>(wq, D, D, pwqkvTh);
    convT_kernel<<<dim3(D / 32, D / 32), 256, 0, s2>>>(wk, D, D, pwqkvTh + DD);
    convT_kernel<<<dim3(D / 32, D / 32), 256, 0, s2>>>(wv, D, D, pwqkvTh + 2 * DD);
    cudaEventRecord(evWqkv, s2);
    convT_kernel<<<dim3(D / 32, D / 32), 256, 0, s2>>>(wo, D, D, pwoTh);
    cudaEventRecord(evWo, s2);
    convT_kernel<<<dim3(FF / 32, D / 32), 256, 0, s2>>>(wfi, D, FF, pwfiTh);
    cudaEventRecord(evWfi, s2);
    convT_kernel<<<dim3(D / 32, FF / 32), 256, 0, s2>>>(wfo, FF, D, pwfoTh);
    cudaEventRecord(evWfo, s2);
    convT_kernel<<<dim3(VOC / 32, D / 32), 256, 0, s2>>>(wout, D, VOC, pwoutTh);
    cudaEventRecord(evWout, s2);

    // main stream
    embed_kernel<<<S, 256>>>(tokens, temb, pemb, px);
    ln_kernel<<<S, 256>>>(px, ln1g, ln1b, phh);
    cudaStreamWaitEvent(0, evWqkv, 0);

    // attention: QKV 1-pass -> flash fused QK+softmax+PV
    tc_gemm<OUT_HI><<<dim3(S / 128, D / 128, 3), 256, GEMM_SMEM>>>(
        (uint16_t*)phh, D, 0, (uint16_t*)pwqkvTh, D, DD, nullptr,
        nullptr, (uint16_t*)pqkvh, D, SD, D, 1.f);
    vtrans_kernel<<<dim3(HD / 32, S / 32, H), 256>>>(pqkvh + 2 * SD, pvth);
    flash_kernel<<<dim3(S / 128, H), 256, FLASH_SMEM>>>(
        pqkvh, pqkvh + SD, pvth, paoh, 0.08838834764831845f);
    cudaStreamWaitEvent(0, evWo, 0);
    tc_gemm<OUT_F32RES><<<dim3(S / 128, D / 128, 1), 256, GEMM_SMEM>>>(
        (uint16_t*)paoh, D, 0, (uint16_t*)pwoTh, D, 0, px,
        px2, nullptr, D, 0, D, 1.f);

    // FFN block
    ln_kernel<<<S, 256>>>(px2, ln2g, ln2b, ph2h);
    cudaStreamWaitEvent(0, evWfi, 0);
    tc_gemm<OUT_RELU_HI><<<dim3(S / 128, FF / 128, 1), 256, GEMM_SMEM>>>(
        (uint16_t*)ph2h, D, 0, (uint16_t*)pwfiTh, D, 0, nullptr,
        nullptr, (uint16_t*)pffh, FF, 0, D, 1.f);
    cudaStreamWaitEvent(0, evWfo, 0);
    tc_gemm<OUT_F32RES><<<dim3(S / 128, D / 128, 1), 256, GEMM_SMEM>>>(
        (uint16_t*)pffh, FF, 0, (uint16_t*)pwfoTh, FF, 0, px2,
        px3, nullptr, D, 0, FF, 1.f);

    // final LN + logits
    ln_kernel<<<S, 256>>>(px3, lnfg, lnfb, phfh);
    cudaStreamWaitEvent(0, evWout, 0);
    tc_gemm<OUT_F32><<<dim3(S / 128, VOC / 128, 1), 256, GEMM_SMEM>>>(
        (uint16_t*)phfh, D, 0, (uint16_t*)pwoutTh, D, 0, nullptr,
        out, nullptr, VOC, 0, D, 1.f);
}

// round 16
// speedup vs baseline: 1.0034x; 1.0034x over previous
#include <cuda_runtime.h>
#include <cuda_bf16.h>
#include <cuda_fp16.h>
#include <stdint.h>
#include <math.h>

typedef __half HALF;

// ---------------- dimensions ----------------
#define S   2048
#define D   2048
#define H   16
#define HD  128
#define FF  8192
#define VOC 32000
#define LN_EPS 1e-5f
#define SD  (S * D)
#define DD  (D * D)

// ---------------- scratch ----------------
__device__ float g_x  [SD];
__device__ float g_x2 [SD];
__device__ float g_x3 [SD];

__device__ HALF g_hh [SD];
__device__ HALF g_h2h[SD];
__device__ HALF g_hfh[SD];
__device__ HALF g_aoh[SD];
__device__ HALF g_ffh[S * FF];
__device__ HALF g_qkvh[3 * SD];       // q,k,v fp16 hi
__device__ HALF g_vth[SD];            // V^T fp16 [H][HD][S]

__device__ HALF g_wqkvTh[3 * DD];
__device__ HALF g_woTh[DD];
__device__ HALF g_wfiTh[D * FF];
__device__ HALF g_wfoTh[D * FF];
__device__ HALF g_woutTh[(size_t)D * VOC];

__device__ int g_tok64;

// ---------------- PTX helpers (plain sm_103-legal) ----------------
__device__ __forceinline__ uint32_t smem_u32(const void* p) {
    uint32_t a;
    asm("{ .reg .u64 t; cvta.to.shared.u64 t, %1; cvt.u32.u64 %0, t; }" : "=r"(a) : "l"(p));
    return a;
}
__device__ __forceinline__ void ldm_x4(uint32_t* r, uint32_t addr) {
    asm volatile("ldmatrix.sync.aligned.m8n8.x4.shared.b16 {%0,%1,%2,%3}, [%4];"
                 : "=r"(r[0]), "=r"(r[1]), "=r"(r[2]), "=r"(r[3]) : "r"(addr));
}
__device__ __forceinline__ void mma_fp16(float* c, const uint32_t* a, const uint32_t* b) {
    asm volatile(
        "mma.sync.aligned.m16n8k16.row.col.f32.f16.f16.f32 "
        "{%0,%1,%2,%3}, {%4,%5,%6,%7}, {%8,%9}, {%0,%1,%2,%3};"
        : "+f"(c[0]), "+f"(c[1]), "+f"(c[2]), "+f"(c[3])
        : "r"(a[0]), "r"(a[1]), "r"(a[2]), "r"(a[3]), "r"(b[0]), "r"(b[1]));
}
#define CP16(dst, src) \
    asm volatile("cp.async.cg.shared.global [%0], [%1], 16;" :: "r"(dst), "l"(src) : "memory")
#define CPCOMMIT() asm volatile("cp.async.commit_group;" ::: "memory")
#define CPWAIT0() asm volatile("cp.async.wait_group 0;" ::: "memory")
#define CPWAIT1() asm volatile("cp.async.wait_group 1;" ::: "memory")

#define SW64(o) ((o) ^ (((o) >> 3) & 0x30))

__device__ __forceinline__ uint32_t pack2h(float a, float b)
{
    __half2 h2 = __halves2half2(__float2half_rn(a), __float2half_rn(b));
    return *reinterpret_cast<uint32_t*>(&h2);
}

// ---------------- token detect ----------------
__global__ void detect_tok_kernel(const int* __restrict__ t)
{
    __shared__ int any;
    if (threadIdx.x == 0) any = 0;
    __syncthreads();
    int local = 0;
    for (int i = threadIdx.x; i < S / 2; i += blockDim.x)
        if (t[2 * i + 1] != 0) local = 1;
    if (local) any = 1;
    __syncthreads();
    if (threadIdx.x == 0) g_tok64 = (any == 0) ? 1 : 0;
}

// ---------------- fused embed + layernorm1: writes fp32 x AND fp16 h ----------------
__global__ void embed_ln_kernel(const int* __restrict__ tok,
                                const float* __restrict__ te,
                                const float* __restrict__ pe,
                                const float* __restrict__ g,
                                const float* __restrict__ b,
                                float* __restrict__ x,
                                HALF* __restrict__ oh)
{
    __shared__ float r1[8], r2[8];
    __shared__ float s_mean, s_inv;
    const int s   = blockIdx.x;
    const int tid = threadIdx.x;
    const int t   = g_tok64 ? tok[2 * s] : tok[s];
    const float4* e = (const float4*)(te + (size_t)t * D);
    const float4* p = (const float4*)(pe + (size_t)s * D);
    float4 e0 = e[tid],       p0 = p[tid];
    float4 e1 = e[tid + 256], p1 = p[tid + 256];
    float4 v0 = make_float4(e0.x + p0.x, e0.y + p0.y, e0.z + p0.z, e0.w + p0.w);
    float4 v1 = make_float4(e1.x + p1.x, e1.y + p1.y, e1.z + p1.z, e1.w + p1.w);
    float4* xr = (float4*)(x + (size_t)s * D);
    xr[tid]       = v0;
    xr[tid + 256] = v1;

    float sum = v0.x + v0.y + v0.z + v0.w + v1.x + v1.y + v1.z + v1.w;
    float sq  = v0.x * v0.x + v0.y * v0.y + v0.z * v0.z + v0.w * v0.w
              + v1.x * v1.x + v1.y * v1.y + v1.z * v1.z + v1.w * v1.w;
#pragma unroll
    for (int o = 16; o; o >>= 1) {
        sum += __shfl_xor_sync(0xffffffffu, sum, o);
        sq  += __shfl_xor_sync(0xffffffffu, sq,  o);
    }
    const int w = tid >> 5;
    if ((tid & 31) == 0) { r1[w] = sum; r2[w] = sq; }
    __syncthreads();
    if (tid == 0) {
        float ts = 0.f, tq = 0.f;
#pragma unroll
        for (int i = 0; i < 8; i++) { ts += r1[i]; tq += r2[i]; }
        const float mean = ts / (float)D;
        const float var  = tq / (float)D - mean * mean;
        s_mean = mean;
        s_inv  = rsqrtf(var + LN_EPS);
    }
    __syncthreads();
    const float mean = s_mean, inv = s_inv;
    const float4* gg = (const float4*)g;
    const float4* bb = (const float4*)b;
    float4 g0 = gg[tid], g1 = gg[tid + 256];
    float4 b0 = bb[tid], b1 = bb[tid + 256];
    float o00 = (v0.x - mean) * inv * g0.x + b0.x;
    float o01 = (v0.y - mean) * inv * g0.y + b0.y;
    float o02 = (v0.z - mean) * inv * g0.z + b0.z;
    float o03 = (v0.w - mean) * inv * g0.w + b0.w;
    float o10 = (v1.x - mean) * inv * g1.x + b1.x;
    float o11 = (v1.y - mean) * inv * g1.y + b1.y;
    float o12 = (v1.z - mean) * inv * g1.z + b1.z;
    float o13 = (v1.w - mean) * inv * g1.w + b1.w;
    const size_t e0o = (size_t)s * D + tid * 4;
    *(uint2*)(oh + e0o)        = make_uint2(pack2h(o00, o01), pack2h(o02, o03));
    *(uint2*)(oh + e0o + 1024) = make_uint2(pack2h(o10, o11), pack2h(o12, o13));
}

// ---------------- weight convert + transpose: fp32 [K][N] -> fp16 hi [N][K] ----------------
__global__ void convT_kernel(const float* __restrict__ src, int K, int N,
                             HALF* __restrict__ dhi)
{
    __shared__ float t[32][33];
    const int n0 = blockIdx.x * 32, k0 = blockIdx.y * 32;
    const int tx = threadIdx.x & 31, ty = threadIdx.x >> 5;
#pragma unroll
    for (int r = 0; r < 4; r++)
        t[ty + 8 * r][tx] = src[(size_t)(k0 + ty + 8 * r) * N + n0 + tx];
    __syncthreads();
#pragma unroll
    for (int r = 0; r < 4; r++) {
        const int n = n0 + ty + 8 * r, k = k0 + tx;
        dhi[(size_t)n * K + k] = __float2half_rn(t[tx][ty + 8 * r]);
    }
}

// ---------------- V transpose: fp16 [S][D] head slice -> fp16 [H][HD][S] ----------------
__global__ void vtrans_kernel(const HALF* __restrict__ vh, HALF* __restrict__ vth)
{
    __shared__ HALF th[32][33];
    const int h = blockIdx.z;
    const int d0 = blockIdx.x * 32, s0 = blockIdx.y * 32;
    const int tx = threadIdx.x & 31, ty = threadIdx.x >> 5;
#pragma unroll
    for (int r = 0; r < 4; r++) {
        const size_t src = (size_t)(s0 + ty + 8 * r) * D + h * HD + d0 + tx;
        th[ty + 8 * r][tx] = vh[src];
    }
    __syncthreads();
#pragma unroll
    for (int r = 0; r < 4; r++) {
        const size_t dst = ((size_t)h * HD + d0 + ty + 8 * r) * S + s0 + tx;
        vth[dst] = th[tx][ty + 8 * r];
    }
}

// ---------------- layernorm: fp32 in -> fp16 hi out ----------------
__global__ void ln_kernel(const float* __restrict__ x,
                          const float* __restrict__ g,
                          const float* __restrict__ b,
                          HALF* __restrict__ oh)
{
    __shared__ float r1[8], r2[8];
    __shared__ float s_mean, s_inv;
    const int s   = blockIdx.x;
    const int tid = threadIdx.x;
    const float4* xr = (const float4*)(x + (size_t)s * D);
    float4 v0 = xr[tid];
    float4 v1 = xr[tid + 256];
    float sum = v0.x + v0.y + v0.z + v0.w + v1.x + v1.y + v1.z + v1.w;
    float sq  = v0.x * v0.x + v0.y * v0.y + v0.z * v0.z + v0.w * v0.w
              + v1.x * v1.x + v1.y * v1.y + v1.z * v1.z + v1.w * v1.w;
#pragma unroll
    for (int o = 16; o; o >>= 1) {
        sum += __shfl_xor_sync(0xffffffffu, sum, o);
        sq  += __shfl_xor_sync(0xffffffffu, sq,  o);
    }
    const int w = tid >> 5;
    if ((tid & 31) == 0) { r1[w] = sum; r2[w] = sq; }
    __syncthreads();
    if (tid == 0) {
        float ts = 0.f, tq = 0.f;
#pragma unroll
        for (int i = 0; i < 8; i++) { ts += r1[i]; tq += r2[i]; }
        const float mean = ts / (float)D;
        const float var  = tq / (float)D - mean * mean;
        s_mean = mean;
        s_inv  = rsqrtf(var + LN_EPS);
    }
    __syncthreads();
    const float mean = s_mean, inv = s_inv;
    const float4* gg = (const float4*)g;
    const float4* bb = (const float4*)b;
    float4 g0 = gg[tid], g1 = gg[tid + 256];
    float4 b0 = bb[tid], b1 = bb[tid + 256];
    float o00 = (v0.x - mean) * inv * g0.x + b0.x;
    float o01 = (v0.y - mean) * inv * g0.y + b0.y;
    float o02 = (v0.z - mean) * inv * g0.z + b0.z;
    float o03 = (v0.w - mean) * inv * g0.w + b0.w;
    float o10 = (v1.x - mean) * inv * g1.x + b1.x;
    float o11 = (v1.y - mean) * inv * g1.y + b1.y;
    float o12 = (v1.z - mean) * inv * g1.z + b1.z;
    float o13 = (v1.w - mean) * inv * g1.w + b1.w;
    const size_t e0 = (size_t)s * D + tid * 4;
    *(uint2*)(oh + e0)        = make_uint2(pack2h(o00, o01), pack2h(o02, o03));
    *(uint2*)(oh + e0 + 1024) = make_uint2(pack2h(o10, o11), pack2h(o12, o13));
}

// ---------------- fused flash attention ----------------
#define FLASH_STAGE 65536
#define FLASH_SMEM  (3 * FLASH_STAGE)

__global__ void __launch_bounds__(256, 1)
flash_kernel(const HALF* __restrict__ q, const HALF* __restrict__ k,
             const HALF* __restrict__ vt, HALF* __restrict__ out, float alpha)
{
    extern __shared__ char smem[];
    const uint32_t sb = smem_u32(smem);
    const int tid = threadIdx.x, wid = tid >> 5, lane = tid & 31;
    const int q0 = blockIdx.x * 128;
    const int h  = blockIdx.y;

    const int rowL = tid >> 1;
    const int half = tid & 1;
    uint32_t so[2][4];
#pragma unroll
    for (int c = 0; c < 2; c++)
#pragma unroll
        for (int u = 0; u < 4; u++)
            so[c][u] = c * 16384 + SW64((uint32_t)(rowL * 128 + half * 64 + u * 16));
    const int gofs = half * 32;

    const int a_row = lane & 15;
    const int a_kc  = (lane >> 4) * 8;
    const int b_row = (lane & 7) + (lane >> 4) * 8;
    const int b_kc  = ((lane >> 3) & 1) * 8;

    {
        const HALF* qp = q + (size_t)(q0 + rowL) * D + h * HD + gofs;
#pragma unroll
        for (int c = 0; c < 2; c++)
#pragma unroll
            for (int u = 0; u < 4; u++)
                CP16(sb + so[c][u], qp + c * 64 + u * 8);
        CPCOMMIT(); CPWAIT0();
    }
    __syncthreads();
    uint32_t qf[8][4];
    {
        const int wq = wid * 16;
#pragma unroll
        for (int j = 0; j < 8; j++) {
            const int kcol = j * 16 + a_kc;
            ldm_x4(qf[j], sb + (kcol >> 6) * 16384
                             + SW64((uint32_t)((wq + a_row) * 128 + (kcol & 63) * 2)));
        }
    }
    __syncthreads();

    const HALF* kbase = k + (size_t)rowL * D + h * HD + gofs;
    const HALF* vbase = vt + ((size_t)h * HD + rowL) * S + gofs;

    auto issue = [&](int t, int st) {
        const uint32_t sB = sb + st * FLASH_STAGE;
        const HALF* kp = kbase + (size_t)(t * 128) * D;
        const HALF* vp = vbase + t * 128;
#pragma unroll
        for (int c = 0; c < 2; c++)
#pragma unroll
            for (int u = 0; u < 4; u++) {
                CP16(sB + so[c][u],         kp + c * 64 + u * 8);
                CP16(sB + 32768 + so[c][u], vp + c * 64 + u * 8);
            }
        CPCOMMIT();
    };

    float oa[16][4];
#pragma unroll
    for (int i = 0; i < 16; i++)
#pragma unroll
        for (int j = 0; j < 4; j++) oa[i][j] = 0.f;
    float m0 = -1e30f, m1 = -1e30f, l0 = 0.f, l1 = 0.f;

    issue(0, 0);
    issue(1, 1);

    for (int t = 0; t < 16; t++) {
        if (t + 1 < 16) { CPWAIT1(); } else { CPWAIT0(); }
        __syncthreads();
        if (t + 2 < 16) issue(t + 2, (t + 2) % 3);

        const uint32_t stK = sb + (t % 3) * FLASH_STAGE;
        const uint32_t stV = stK + 32768;

        float s[16][4];
#pragma unroll
        for (int i = 0; i < 16; i++)
#pragma unroll
            for (int j = 0; j < 4; j++) s[i][j] = 0.f;
#pragma unroll
        for (int j = 0; j < 8; j++) {
            const int kcol = j * 16 + b_kc;
            const uint32_t kadd = stK + (kcol >> 6) * 16384;
            const uint32_t kc2 = (kcol & 63) * 2;
#pragma unroll
            for (int nt2 = 0; nt2 < 8; nt2++) {
                uint32_t bh[4];
                ldm_x4(bh, kadd + SW64((uint32_t)((nt2 * 16 + b_row) * 128) + kc2));
                mma_fp16(s[2 * nt2],     qf[j], bh);
                mma_fp16(s[2 * nt2 + 1], qf[j], bh + 2);
            }
        }

        float tm0 = -1e30f, tm1 = -1e30f;
#pragma unroll
        for (int nt = 0; nt < 16; nt++) {
            s[nt][0] *= alpha; s[nt][1] *= alpha;
            s[nt][2] *= alpha; s[nt][3] *= alpha;
            tm0 = fmaxf(tm0, fmaxf(s[nt][0], s[nt][1]));
            tm1 = fmaxf(tm1, fmaxf(s[nt][2], s[nt][3]));
        }
        tm0 = fmaxf(tm0, __shfl_xor_sync(0xffffffffu, tm0, 1));
        tm0 = fmaxf(tm0, __shfl_xor_sync(0xffffffffu, tm0, 2));
        tm1 = fmaxf(tm1, __shfl_xor_sync(0xffffffffu, tm1, 1));
        tm1 = fmaxf(tm1, __shfl_xor_sync(0xffffffffu, tm1, 2));
        const float nm0 = fmaxf(m0, tm0), nm1 = fmaxf(m1, tm1);
        const float f0 = __expf(m0 - nm0), f1 = __expf(m1 - nm1);
        m0 = nm0; m1 = nm1;
        float ps0 = 0.f, ps1 = 0.f;
#pragma unroll
        for (int nt = 0; nt < 16; nt++) {
            s[nt][0] = __expf(s[nt][0] - nm0); ps0 += s[nt][0];
            s[nt][1] = __expf(s[nt][1] - nm0); ps0 += s[nt][1];
            s[nt][2] = __expf(s[nt][2] - nm1); ps1 += s[nt][2];
            s[nt][3] = __expf(s[nt][3] - nm1); ps1 += s[nt][3];
        }
        ps0 += __shfl_xor_sync(0xffffffffu, ps0, 1);
        ps0 += __shfl_xor_sync(0xffffffffu, ps0, 2);
        ps1 += __shfl_xor_sync(0xffffffffu, ps1, 1);
        ps1 += __shfl_xor_sync(0xffffffffu, ps1, 2);
        l0 = l0 * f0 + ps0;
        l1 = l1 * f1 + ps1;
#pragma unroll
        for (int vtt = 0; vtt < 16; vtt++) {
            oa[vtt][0] *= f0; oa[vtt][1] *= f0;
            oa[vtt][2] *= f1; oa[vtt][3] *= f1;
        }

#pragma unroll
        for (int ks = 0; ks < 8; ks++) {
            uint32_t af[4];
            af[0] = pack2h(s[2 * ks][0],     s[2 * ks][1]);
            af[1] = pack2h(s[2 * ks][2],     s[2 * ks][3]);
            af[2] = pack2h(s[2 * ks + 1][0], s[2 * ks + 1][1]);
            af[3] = pack2h(s[2 * ks + 1][2], s[2 * ks + 1][3]);
            const int scol = ks * 16 + b_kc;
            const uint32_t vadd = stV + (scol >> 6) * 16384;
            const uint32_t sc2 = (scol & 63) * 2;
#pragma unroll
            for (int vt2 = 0; vt2 < 8; vt2++) {
                uint32_t bh[4];
                ldm_x4(bh, vadd + SW64((uint32_t)((vt2 * 16 + b_row) * 128) + sc2));
                mma_fp16(oa[2 * vt2],     af, bh);
                mma_fp16(oa[2 * vt2 + 1], af, bh + 2);
            }
        }
    }

    const float i0 = 1.f / l0, i1 = 1.f / l1;
    const int r0 = q0 + wid * 16 + (lane >> 2);
    HALF* op0 = out + (size_t)r0 * D + h * HD + (lane & 3) * 2;
    HALF* op1 = op0 + (size_t)8 * D;
#pragma unroll
    for (int vtt = 0; vtt < 16; vtt++) {
        *(uint32_t*)(op0 + vtt * 8) = pack2h(oa[vtt][0] * i0, oa[vtt][1] * i0);
        *(uint32_t*)(op1 + vtt * 8) = pack2h(oa[vtt][2] * i1, oa[vtt][3] * i1);
    }
}

// ---------------- cp.async pipelined GEMM (fp16, 1-pass, BK=64; R14 mainloop) ----------------
#define OUT_F32       0
#define OUT_F32RES    1
#define OUT_RELU_HI   4
#define OUT_HI        5

#define GSTAGE 32768
#define GEMM_SMEM (3 * GSTAGE)

template <int OUT>
__global__ void __launch_bounds__(256, 2)
tc_gemm(const uint16_t* __restrict__ Ah, int lda, long long sA,
        const uint16_t* __restrict__ Bh, int ldb, long long sB,
        const float* __restrict__ Res,
        float* __restrict__ Cf, uint16_t* __restrict__ Chi,
        int ldc, long long sC, int K, float alpha)
{
    extern __shared__ char smem[];
    const uint32_t sb = smem_u32(smem);
    const int tid = threadIdx.x, wid = tid >> 5, lane = tid & 31;
    const int z = blockIdx.z;
    Ah += (size_t)z * sA;
    Bh += (size_t)z * sB;
    const int m0 = blockIdx.x * 128;   // M fast-varying
    const int n0 = blockIdx.y * 128;
    const int wm = (wid & 3) * 32;
    const int wn = (wid >> 2) * 64;

    // loader (512B/warp window, conflict-free + coalesced)
    const int rowL = tid >> 2;
    const int cL   = tid & 3;
    const uint32_t o0 = SW64((uint32_t)(rowL * 64 + cL * 16));
    const uint32_t o1 = SW64((uint32_t)((rowL + 64) * 64 + cL * 16));
    const uint16_t* aht = Ah + (size_t)(m0 + rowL) * lda + cL * 8;
    const uint16_t* bht = Bh + (size_t)(n0 + rowL) * ldb + cL * 8;
    const size_t a64 = (size_t)64 * lda;
    const size_t b64 = (size_t)64 * ldb;

    auto issue = [&](int idx, int s) {
        const uint32_t st = sb + s * GSTAGE;
        const uint16_t* a1 = aht + idx * 64;
        const uint16_t* b1 = bht + idx * 64;
        CP16(st + o0,          a1);
        CP16(st + o1,          a1 + a64);
        CP16(st + 8192 + o0,   a1 + 32);
        CP16(st + 8192 + o1,   a1 + 32 + a64);
        CP16(st + 16384 + o0,  b1);
        CP16(st + 16384 + o1,  b1 + b64);
        CP16(st + 24576 + o0,  b1 + 32);
        CP16(st + 24576 + o1,  b1 + 32 + b64);
        CPCOMMIT();
    };

    float acc[2][8][4];
#pragma unroll
    for (int i = 0; i < 2; i++)
#pragma unroll
        for (int j = 0; j < 8; j++)
#pragma unroll
            for (int q = 0; q < 4; q++) acc[i][j][q] = 0.f;

    const int a_row = lane & 15;
    const int a_kc  = (lane >> 4) * 8;
    const int b_row = (lane & 7) + (lane >> 4) * 8;
    const int b_kc  = ((lane >> 3) & 1) * 8;

    const int nch = K >> 6;
    issue(0, 0);
    if (nch > 1) issue(1, 1);

    for (int i = 0; i < nch; i++) {
        if (i + 1 < nch) { CPWAIT1(); } else { CPWAIT0(); }
        __syncthreads();                       // single barrier per chunk
        if (i + 2 < nch) issue(i + 2, (i + 2) % 3);

        const uint32_t st  = sb + (i % 3) * GSTAGE;
#pragma unroll
        for (int ks = 0; ks < 4; ks++) {
            const uint32_t blk = (uint32_t)(ks >> 1) * 8192;
            const uint32_t akc2 = (uint32_t)(((ks & 1) * 16 + a_kc) * 2);
            const uint32_t bkc2 = (uint32_t)(((ks & 1) * 16 + b_kc) * 2);
            uint32_t ah[2][4];
#pragma unroll
            for (int mf = 0; mf < 2; mf++)
                ldm_x4(ah[mf], st + blk
                       + SW64((uint32_t)((wm + mf * 16 + a_row) * 64) + akc2));
#pragma unroll
            for (int p = 0; p < 4; p++) {
                uint32_t bh[4];
                ldm_x4(bh, st + 16384 + blk
                       + SW64((uint32_t)((wn + p * 16 + b_row) * 64) + bkc2));
#pragma unroll
                for (int mf = 0; mf < 2; mf++) {
                    mma_fp16(acc[mf][2 * p],     ah[mf], bh);
                    mma_fp16(acc[mf][2 * p + 1], ah[mf], bh + 2);
                }
            }
        }
    }

    const int r  = lane >> 2;
    const int c2 = (lane & 3) * 2;
#pragma unroll
    for (int mf = 0; mf < 2; mf++) {
#pragma unroll
        for (int hh = 0; hh < 2; hh++) {
            const int m = m0 + wm + mf * 16 + r + 8 * hh;
            const size_t rofs = (size_t)z * sC + (size_t)m * ldc + n0 + wn;
#pragma unroll
            for (int nf = 0; nf < 8; nf++) {
                float x0 = acc[mf][nf][2 * hh]     * alpha;
                float x1 = acc[mf][nf][2 * hh + 1] * alpha;
                const int nn = nf * 8 + c2;
                if (OUT == OUT_F32RES) {
                    const float2 rr = *(const float2*)(Res + (size_t)m * ldc + n0 + wn + nn);
                    x0 += rr.x; x1 += rr.y;
                } else if (OUT == OUT_RELU_HI) {
                    x0 = fmaxf(x0, 0.f); x1 = fmaxf(x1, 0.f);
                }
                if (OUT == OUT_F32 || OUT == OUT_F32RES) {
                    *(float2*)(Cf + rofs + nn) = make_float2(x0, x1);
                } else {
                    *(uint32_t*)(Chi + rofs + nn) = pack2h(x0, x1);
                }
            }
        }
    }
}

// ---------------- launch ----------------
extern "C" void kernel_launch(void* const* d_in, const int* in_sizes, int n_in,
                              void* d_out, int out_size)
{
    const int*   tokens = (const int*)d_in[0];
    const float* temb   = (const float*)d_in[1];
    const float* pemb   = (const float*)d_in[2];
    const float* wq     = (const float*)d_in[3];
    const float* wk     = (const float*)d_in[4];
    const float* wv     = (const float*)d_in[5];
    const float* wo     = (const float*)d_in[6];
    const float* wfi    = (const float*)d_in[7];
    const float* wfo    = (const float*)d_in[8];
    const float* ln1g   = (const float*)d_in[9];
    const float* ln1b   = (const float*)d_in[10];
    const float* ln2g   = (const float*)d_in[11];
    const float* ln2b   = (const float*)d_in[12];
    const float* lnfg   = (const float*)d_in[13];
    const float* lnfb   = (const float*)d_in[14];
    const float* wout   = (const float*)d_in[15];
    float*       out    = (float*)d_out;

    float *px, *px2, *px3;
    HALF *phh, *ph2h, *phfh, *paoh, *pffh, *pvth, *pqkvh;
    HALF *pwqkvTh, *pwoTh, *pwfiTh, *pwfoTh, *pwoutTh;
    cudaGetSymbolAddress((void**)&px,   g_x);
    cudaGetSymbolAddress((void**)&px2,  g_x2);
    cudaGetSymbolAddress((void**)&px3,  g_x3);
    cudaGetSymbolAddress((void**)&phh,  g_hh);
    cudaGetSymbolAddress((void**)&ph2h, g_h2h);
    cudaGetSymbolAddress((void**)&phfh, g_hfh);
    cudaGetSymbolAddress((void**)&paoh, g_aoh);
    cudaGetSymbolAddress((void**)&pffh, g_ffh);
    cudaGetSymbolAddress((void**)&pvth, g_vth);
    cudaGetSymbolAddress((void**)&pqkvh, g_qkvh);
    cudaGetSymbolAddress((void**)&pwqkvTh, g_wqkvTh);
    cudaGetSymbolAddress((void**)&pwoTh, g_woTh);
    cudaGetSymbolAddress((void**)&pwfiTh, g_wfiTh);
    cudaGetSymbolAddress((void**)&pwfoTh, g_wfoTh);
    cudaGetSymbolAddress((void**)&pwoutTh, g_woutTh);

    cudaFuncSetAttribute(tc_gemm<OUT_HI>,
                         cudaFuncAttributeMaxDynamicSharedMemorySize, GEMM_SMEM);
    cudaFuncSetAttribute(tc_gemm<OUT_F32RES>,
                         cudaFuncAttributeMaxDynamicSharedMemorySize, GEMM_SMEM);
    cudaFuncSetAttribute(tc_gemm<OUT_RELU_HI>,
                         cudaFuncAttributeMaxDynamicSharedMemorySize, GEMM_SMEM);
    cudaFuncSetAttribute(tc_gemm<OUT_F32>,
                         cudaFuncAttributeMaxDynamicSharedMemorySize, GEMM_SMEM);
    cudaFuncSetAttribute(flash_kernel,
                         cudaFuncAttributeMaxDynamicSharedMemorySize, FLASH_SMEM);

    // ---- side stream for all weight conversions ----
    cudaStream_t s2;
    cudaStreamCreateWithFlags(&s2, cudaStreamNonBlocking);
    cudaEvent_t evFork, evWqkv, evWo, evWfi, evWfo, evWout;
    cudaEventCreateWithFlags(&evFork, cudaEventDisableTiming);
    cudaEventCreateWithFlags(&evWqkv, cudaEventDisableTiming);
    cudaEventCreateWithFlags(&evWo,   cudaEventDisableTiming);
    cudaEventCreateWithFlags(&evWfi,  cudaEventDisableTiming);
    cudaEventCreateWithFlags(&evWfo,  cudaEventDisableTiming);
    cudaEventCreateWithFlags(&evWout, cudaEventDisableTiming);

    detect_tok_kernel<<<1, 256>>>(tokens);
    cudaEventRecord(evFork, 0);
    cudaStreamWaitEvent(s2, evFork, 0);

    convT_kernel<<<dim3(D / 32, D / 32), 256, 0, s2>>>(wq, D, D, pwqkvTh);
    convT_kernel<<<dim3(D / 32, D / 32), 256, 0, s2>>>(wk, D, D, pwqkvTh + DD);
    convT_kernel<<<dim3(D / 32, D / 32), 256, 0, s2>>>(wv, D, D, pwqkvTh + 2 * DD);
    cudaEventRecord(evWqkv, s2);
    convT_kernel<<<dim3(D / 32, D / 32), 256, 0, s2>>>(wo, D, D, pwoTh);
    cudaEventRecord(evWo, s2);
    convT_kernel<<<dim3(FF / 32, D / 32), 256, 0, s2>>>(wfi, D, FF, pwfiTh);
    cudaEventRecord(evWfi, s2);
    convT_kernel<<<dim3(D / 32, FF / 32), 256, 0, s2>>>(wfo, FF, D, pwfoTh);
    cudaEventRecord(evWfo, s2);
    convT_kernel<<<dim3(VOC / 32, D / 32), 256, 0, s2>>>(wout, D, VOC, pwoutTh);
    cudaEventRecord(evWout, s2);

    // main stream: fused embed + ln1 (overlaps wqkv conversion)
    embed_ln_kernel<<<S, 256>>>(tokens, temb, pemb, ln1g, ln1b, px, phh);
    cudaStreamWaitEvent(0, evWqkv, 0);

    // attention: QKV 1-pass -> flash fused QK+softmax+PV
    tc_gemm<OUT_HI><<<dim3(S / 128, D / 128, 3), 256, GEMM_SMEM>>>(
        (uint16_t*)phh, D, 0, (uint16_t*)pwqkvTh, D, DD, nullptr,
        nullptr, (uint16_t*)pqkvh, D, SD, D, 1.f);
    vtrans_kernel<<<dim3(HD / 32, S / 32, H), 256>>>(pqkvh + 2 * SD, pvth);
    flash_kernel<<<dim3(S / 128, H), 256, FLASH_SMEM>>>(
        pqkvh, pqkvh + SD, pvth, paoh, 0.08838834764831845f);
    cudaStreamWaitEvent(0, evWo, 0);
    tc_gemm<OUT_F32RES><<<dim3(S / 128, D / 128, 1), 256, GEMM_SMEM>>>(
        (uint16_t*)paoh, D, 0, (uint16_t*)pwoTh, D, 0, px,
        px2, nullptr, D, 0, D, 1.f);

    // FFN block
    ln_kernel<<<S, 256>>>(px2, ln2g, ln2b, ph2h);
    cudaStreamWaitEvent(0, evWfi, 0);
    tc_gemm<OUT_RELU_HI><<<dim3(S / 128, FF / 128, 1), 256, GEMM_SMEM>>>(
        (uint16_t*)ph2h, D, 0, (uint16_t*)pwfiTh, D, 0, nullptr,
        nullptr, (uint16_t*)pffh, FF, 0, D, 1.f);
    cudaStreamWaitEvent(0, evWfo, 0);
    tc_gemm<OUT_F32RES><<<dim3(S / 128, D / 128, 1), 256, GEMM_SMEM>>>(
        (uint16_t*)pffh, FF, 0, (uint16_t*)pwfoTh, FF, 0, px2,
        px3, nullptr, D, 0, FF, 1.f);

    // final LN + logits
    ln_kernel<<<S, 256>>>(px3, lnfg, lnfb, phfh);
    cudaStreamWaitEvent(0, evWout, 0);
    tc_gemm<OUT_F32><<<dim3(S / 128, VOC / 128, 1), 256, GEMM_SMEM>>>(
        (uint16_t*)phfh, D, 0, (uint16_t*)pwoutTh, D, 0, nullptr,
        out, nullptr, VOC, 0, D, 1.f);
}

// round 17
// speedup vs baseline: 1.0179x; 1.0144x over previous
#include <cuda_runtime.h>
#include <cuda_bf16.h>
#include <cuda_fp16.h>
#include <stdint.h>
#include <math.h>

typedef __half HALF;

// ---------------- dimensions ----------------
#define S   2048
#define D   2048
#define H   16
#define HD  128
#define FF  8192
#define VOC 32000
#define LN_EPS 1e-5f
#define SD  (S * D)
#define DD  (D * D)

// ---------------- scratch ----------------
__device__ float g_x  [SD];
__device__ float g_x2 [SD];
__device__ float g_x3 [SD];

__device__ HALF g_hh [SD];
__device__ HALF g_h2h[SD];
__device__ HALF g_hfh[SD];
__device__ HALF g_aoh[SD];
__device__ HALF g_ffh[S * FF];
__device__ HALF g_qkvh[3 * SD];       // q,k,v fp16 hi
__device__ HALF g_vth[SD];            // V^T fp16 [H][HD][S]

__device__ HALF g_wqkvTh[3 * DD];
__device__ HALF g_woTh[DD];
__device__ HALF g_wfiTh[D * FF];
__device__ HALF g_wfoTh[D * FF];
__device__ HALF g_woutTh[(size_t)D * VOC];

__device__ int g_tok64;

// ---------------- PTX helpers (plain sm_103-legal) ----------------
__device__ __forceinline__ uint32_t smem_u32(const void* p) {
    uint32_t a;
    asm("{ .reg .u64 t; cvta.to.shared.u64 t, %1; cvt.u32.u64 %0, t; }" : "=r"(a) : "l"(p));
    return a;
}
__device__ __forceinline__ void ldm_x4(uint32_t* r, uint32_t addr) {
    asm volatile("ldmatrix.sync.aligned.m8n8.x4.shared.b16 {%0,%1,%2,%3}, [%4];"
                 : "=r"(r[0]), "=r"(r[1]), "=r"(r[2]), "=r"(r[3]) : "r"(addr));
}
__device__ __forceinline__ void mma_fp16(float* c, const uint32_t* a, const uint32_t* b) {
    asm volatile(
        "mma.sync.aligned.m16n8k16.row.col.f32.f16.f16.f32 "
        "{%0,%1,%2,%3}, {%4,%5,%6,%7}, {%8,%9}, {%0,%1,%2,%3};"
        : "+f"(c[0]), "+f"(c[1]), "+f"(c[2]), "+f"(c[3])
        : "r"(a[0]), "r"(a[1]), "r"(a[2]), "r"(a[3]), "r"(b[0]), "r"(b[1]));
}
#define CP16(dst, src) \
    asm volatile("cp.async.cg.shared.global [%0], [%1], 16;" :: "r"(dst), "l"(src) : "memory")
#define CPCOMMIT() asm volatile("cp.async.commit_group;" ::: "memory")
#define CPWAIT0() asm volatile("cp.async.wait_group 0;" ::: "memory")
#define CPWAIT1() asm volatile("cp.async.wait_group 1;" ::: "memory")

#define SW64(o) ((o) ^ (((o) >> 3) & 0x30))

__device__ __forceinline__ uint32_t pack2h(float a, float b)
{
    __half2 h2 = __halves2half2(__float2half_rn(a), __float2half_rn(b));
    return *reinterpret_cast<uint32_t*>(&h2);
}

// ---------------- token detect ----------------
__global__ void detect_tok_kernel(const int* __restrict__ t)
{
    __shared__ int any;
    if (threadIdx.x == 0) any = 0;
    __syncthreads();
    int local = 0;
    for (int i = threadIdx.x; i < S / 2; i += blockDim.x)
        if (t[2 * i + 1] != 0) local = 1;
    if (local) any = 1;
    __syncthreads();
    if (threadIdx.x == 0) g_tok64 = (any == 0) ? 1 : 0;
}

// ---------------- fused embed + layernorm1: writes fp32 x AND fp16 h ----------------
__global__ void embed_ln_kernel(const int* __restrict__ tok,
                                const float* __restrict__ te,
                                const float* __restrict__ pe,
                                const float* __restrict__ g,
                                const float* __restrict__ b,
                                float* __restrict__ x,
                                HALF* __restrict__ oh)
{
    __shared__ float r1[8], r2[8];
    __shared__ float s_mean, s_inv;
    const int s   = blockIdx.x;
    const int tid = threadIdx.x;
    const int t   = g_tok64 ? tok[2 * s] : tok[s];
    const float4* e = (const float4*)(te + (size_t)t * D);
    const float4* p = (const float4*)(pe + (size_t)s * D);
    float4 e0 = e[tid],       p0 = p[tid];
    float4 e1 = e[tid + 256], p1 = p[tid + 256];
    float4 v0 = make_float4(e0.x + p0.x, e0.y + p0.y, e0.z + p0.z, e0.w + p0.w);
    float4 v1 = make_float4(e1.x + p1.x, e1.y + p1.y, e1.z + p1.z, e1.w + p1.w);
    float4* xr = (float4*)(x + (size_t)s * D);
    xr[tid]       = v0;
    xr[tid + 256] = v1;

    float sum = v0.x + v0.y + v0.z + v0.w + v1.x + v1.y + v1.z + v1.w;
    float sq  = v0.x * v0.x + v0.y * v0.y + v0.z * v0.z + v0.w * v0.w
              + v1.x * v1.x + v1.y * v1.y + v1.z * v1.z + v1.w * v1.w;
#pragma unroll
    for (int o = 16; o; o >>= 1) {
        sum += __shfl_xor_sync(0xffffffffu, sum, o);
        sq  += __shfl_xor_sync(0xffffffffu, sq,  o);
    }
    const int w = tid >> 5;
    if ((tid & 31) == 0) { r1[w] = sum; r2[w] = sq; }
    __syncthreads();
    if (tid == 0) {
        float ts = 0.f, tq = 0.f;
#pragma unroll
        for (int i = 0; i < 8; i++) { ts += r1[i]; tq += r2[i]; }
        const float mean = ts / (float)D;
        const float var  = tq / (float)D - mean * mean;
        s_mean = mean;
        s_inv  = rsqrtf(var + LN_EPS);
    }
    __syncthreads();
    const float mean = s_mean, inv = s_inv;
    const float4* gg = (const float4*)g;
    const float4* bb = (const float4*)b;
    float4 g0 = gg[tid], g1 = gg[tid + 256];
    float4 b0 = bb[tid], b1 = bb[tid + 256];
    float o00 = (v0.x - mean) * inv * g0.x + b0.x;
    float o01 = (v0.y - mean) * inv * g0.y + b0.y;
    float o02 = (v0.z - mean) * inv * g0.z + b0.z;
    float o03 = (v0.w - mean) * inv * g0.w + b0.w;
    float o10 = (v1.x - mean) * inv * g1.x + b1.x;
    float o11 = (v1.y - mean) * inv * g1.y + b1.y;
    float o12 = (v1.z - mean) * inv * g1.z + b1.z;
    float o13 = (v1.w - mean) * inv * g1.w + b1.w;
    const size_t e0o = (size_t)s * D + tid * 4;
    *(uint2*)(oh + e0o)        = make_uint2(pack2h(o00, o01), pack2h(o02, o03));
    *(uint2*)(oh + e0o + 1024) = make_uint2(pack2h(o10, o11), pack2h(o12, o13));
}

// ---------------- weight convert + transpose: fp32 [K][N] -> fp16 hi [N][K] ----------------
// Tile 64k x 32n; half2 (128B/warp) coalesced stores. Grid (N/32, K/64).
__global__ void convT_kernel(const float* __restrict__ src, int K, int N,
                             HALF* __restrict__ dhi)
{
    __shared__ float t[64][33];
    const int n0 = blockIdx.x * 32, k0 = blockIdx.y * 64;
    const int tx = threadIdx.x & 31, ty = threadIdx.x >> 5;
#pragma unroll
    for (int r = 0; r < 8; r++)
        t[ty + 8 * r][tx] = src[(size_t)(k0 + ty + 8 * r) * N + n0 + tx];
    __syncthreads();
    const int kk = tx;            // uint32 index along k (2 halves)
#pragma unroll
    for (int rr = 0; rr < 4; rr++) {
        const int n = rr * 8 + ty;
        const uint32_t v = pack2h(t[2 * kk][n], t[2 * kk + 1][n]);
        *(uint32_t*)(dhi + (size_t)(n0 + n) * K + k0 + 2 * kk) = v;
    }
}

// ---------------- V transpose: fp16 [S][D] head slice -> fp16 [H][HD][S] ----------------
__global__ void vtrans_kernel(const HALF* __restrict__ vh, HALF* __restrict__ vth)
{
    __shared__ HALF th[32][33];
    const int h = blockIdx.z;
    const int d0 = blockIdx.x * 32, s0 = blockIdx.y * 32;
    const int tx = threadIdx.x & 31, ty = threadIdx.x >> 5;
#pragma unroll
    for (int r = 0; r < 4; r++) {
        const size_t src = (size_t)(s0 + ty + 8 * r) * D + h * HD + d0 + tx;
        th[ty + 8 * r][tx] = vh[src];
    }
    __syncthreads();
#pragma unroll
    for (int r = 0; r < 4; r++) {
        const size_t dst = ((size_t)h * HD + d0 + ty + 8 * r) * S + s0 + tx;
        vth[dst] = th[tx][ty + 8 * r];
    }
}

// ---------------- layernorm: fp32 in -> fp16 hi out ----------------
__global__ void ln_kernel(const float* __restrict__ x,
                          const float* __restrict__ g,
                          const float* __restrict__ b,
                          HALF* __restrict__ oh)
{
    __shared__ float r1[8], r2[8];
    __shared__ float s_mean, s_inv;
    const int s   = blockIdx.x;
    const int tid = threadIdx.x;
    const float4* xr = (const float4*)(x + (size_t)s * D);
    float4 v0 = xr[tid];
    float4 v1 = xr[tid + 256];
    float sum = v0.x + v0.y + v0.z + v0.w + v1.x + v1.y + v1.z + v1.w;
    float sq  = v0.x * v0.x + v0.y * v0.y + v0.z * v0.z + v0.w * v0.w
              + v1.x * v1.x + v1.y * v1.y + v1.z * v1.z + v1.w * v1.w;
#pragma unroll
    for (int o = 16; o; o >>= 1) {
        sum += __shfl_xor_sync(0xffffffffu, sum, o);
        sq  += __shfl_xor_sync(0xffffffffu, sq,  o);
    }
    const int w = tid >> 5;
    if ((tid & 31) == 0) { r1[w] = sum; r2[w] = sq; }
    __syncthreads();
    if (tid == 0) {
        float ts = 0.f, tq = 0.f;
#pragma unroll
        for (int i = 0; i < 8; i++) { ts += r1[i]; tq += r2[i]; }
        const float mean = ts / (float)D;
        const float var  = tq / (float)D - mean * mean;
        s_mean = mean;
        s_inv  = rsqrtf(var + LN_EPS);
    }
    __syncthreads();
    const float mean = s_mean, inv = s_inv;
    const float4* gg = (const float4*)g;
    const float4* bb = (const float4*)b;
    float4 g0 = gg[tid], g1 = gg[tid + 256];
    float4 b0 = bb[tid], b1 = bb[tid + 256];
    float o00 = (v0.x - mean) * inv * g0.x + b0.x;
    float o01 = (v0.y - mean) * inv * g0.y + b0.y;
    float o02 = (v0.z - mean) * inv * g0.z + b0.z;
    float o03 = (v0.w - mean) * inv * g0.w + b0.w;
    float o10 = (v1.x - mean) * inv * g1.x + b1.x;
    float o11 = (v1.y - mean) * inv * g1.y + b1.y;
    float o12 = (v1.z - mean) * inv * g1.z + b1.z;
    float o13 = (v1.w - mean) * inv * g1.w + b1.w;
    const size_t e0 = (size_t)s * D + tid * 4;
    *(uint2*)(oh + e0)        = make_uint2(pack2h(o00, o01), pack2h(o02, o03));
    *(uint2*)(oh + e0 + 1024) = make_uint2(pack2h(o10, o11), pack2h(o12, o13));
}

// ---------------- fused flash attention ----------------
#define FLASH_STAGE 65536
#define FLASH_SMEM  (3 * FLASH_STAGE)

__global__ void __launch_bounds__(256, 1)
flash_kernel(const HALF* __restrict__ q, const HALF* __restrict__ k,
             const HALF* __restrict__ vt, HALF* __restrict__ out, float alpha)
{
    extern __shared__ char smem[];
    const uint32_t sb = smem_u32(smem);
    const int tid = threadIdx.x, wid = tid >> 5, lane = tid & 31;
    const int q0 = blockIdx.x * 128;
    const int h  = blockIdx.y;

    const int rowL = tid >> 1;
    const int half = tid & 1;
    uint32_t so[2][4];
#pragma unroll
    for (int c = 0; c < 2; c++)
#pragma unroll
        for (int u = 0; u < 4; u++)
            so[c][u] = c * 16384 + SW64((uint32_t)(rowL * 128 + half * 64 + u * 16));
    const int gofs = half * 32;

    const int a_row = lane & 15;
    const int a_kc  = (lane >> 4) * 8;
    const int b_row = (lane & 7) + (lane >> 4) * 8;
    const int b_kc  = ((lane >> 3) & 1) * 8;

    {
        const HALF* qp = q + (size_t)(q0 + rowL) * D + h * HD + gofs;
#pragma unroll
        for (int c = 0; c < 2; c++)
#pragma unroll
            for (int u = 0; u < 4; u++)
                CP16(sb + so[c][u], qp + c * 64 + u * 8);
        CPCOMMIT(); CPWAIT0();
    }
    __syncthreads();
    uint32_t qf[8][4];
    {
        const int wq = wid * 16;
#pragma unroll
        for (int j = 0; j < 8; j++) {
            const int kcol = j * 16 + a_kc;
            ldm_x4(qf[j], sb + (kcol >> 6) * 16384
                             + SW64((uint32_t)((wq + a_row) * 128 + (kcol & 63) * 2)));
        }
    }
    __syncthreads();

    const HALF* kbase = k + (size_t)rowL * D + h * HD + gofs;
    const HALF* vbase = vt + ((size_t)h * HD + rowL) * S + gofs;

    auto issue = [&](int t, int st) {
        const uint32_t sB = sb + st * FLASH_STAGE;
        const HALF* kp = kbase + (size_t)(t * 128) * D;
        const HALF* vp = vbase + t * 128;
#pragma unroll
        for (int c = 0; c < 2; c++)
#pragma unroll
            for (int u = 0; u < 4; u++) {
                CP16(sB + so[c][u],         kp + c * 64 + u * 8);
                CP16(sB + 32768 + so[c][u], vp + c * 64 + u * 8);
            }
        CPCOMMIT();
    };

    float oa[16][4];
#pragma unroll
    for (int i = 0; i < 16; i++)
#pragma unroll
        for (int j = 0; j < 4; j++) oa[i][j] = 0.f;
    float m0 = -1e30f, m1 = -1e30f, l0 = 0.f, l1 = 0.f;

    issue(0, 0);
    issue(1, 1);

    for (int t = 0; t < 16; t++) {
        if (t + 1 < 16) { CPWAIT1(); } else { CPWAIT0(); }
        __syncthreads();
        if (t + 2 < 16) issue(t + 2, (t + 2) % 3);

        const uint32_t stK = sb + (t % 3) * FLASH_STAGE;
        const uint32_t stV = stK + 32768;

        float s[16][4];
#pragma unroll
        for (int i = 0; i < 16; i++)
#pragma unroll
            for (int j = 0; j < 4; j++) s[i][j] = 0.f;
#pragma unroll
        for (int j = 0; j < 8; j++) {
            const int kcol = j * 16 + b_kc;
            const uint32_t kadd = stK + (kcol >> 6) * 16384;
            const uint32_t kc2 = (kcol & 63) * 2;
#pragma unroll
            for (int nt2 = 0; nt2 < 8; nt2++) {
                uint32_t bh[4];
                ldm_x4(bh, kadd + SW64((uint32_t)((nt2 * 16 + b_row) * 128) + kc2));
                mma_fp16(s[2 * nt2],     qf[j], bh);
                mma_fp16(s[2 * nt2 + 1], qf[j], bh + 2);
            }
        }

        float tm0 = -1e30f, tm1 = -1e30f;
#pragma unroll
        for (int nt = 0; nt < 16; nt++) {
            s[nt][0] *= alpha; s[nt][1] *= alpha;
            s[nt][2] *= alpha; s[nt][3] *= alpha;
            tm0 = fmaxf(tm0, fmaxf(s[nt][0], s[nt][1]));
            tm1 = fmaxf(tm1, fmaxf(s[nt][2], s[nt][3]));
        }
        tm0 = fmaxf(tm0, __shfl_xor_sync(0xffffffffu, tm0, 1));
        tm0 = fmaxf(tm0, __shfl_xor_sync(0xffffffffu, tm0, 2));
        tm1 = fmaxf(tm1, __shfl_xor_sync(0xffffffffu, tm1, 1));
        tm1 = fmaxf(tm1, __shfl_xor_sync(0xffffffffu, tm1, 2));
        const float nm0 = fmaxf(m0, tm0), nm1 = fmaxf(m1, tm1);
        const float f0 = __expf(m0 - nm0), f1 = __expf(m1 - nm1);
        m0 = nm0; m1 = nm1;
        float ps0 = 0.f, ps1 = 0.f;
#pragma unroll
        for (int nt = 0; nt < 16; nt++) {
            s[nt][0] = __expf(s[nt][0] - nm0); ps0 += s[nt][0];
            s[nt][1] = __expf(s[nt][1] - nm0); ps0 += s[nt][1];
            s[nt][2] = __expf(s[nt][2] - nm1); ps1 += s[nt][2];
            s[nt][3] = __expf(s[nt][3] - nm1); ps1 += s[nt][3];
        }
        ps0 += __shfl_xor_sync(0xffffffffu, ps0, 1);
        ps0 += __shfl_xor_sync(0xffffffffu, ps0, 2);
        ps1 += __shfl_xor_sync(0xffffffffu, ps1, 1);
        ps1 += __shfl_xor_sync(0xffffffffu, ps1, 2);
        l0 = l0 * f0 + ps0;
        l1 = l1 * f1 + ps1;
#pragma unroll
        for (int vtt = 0; vtt < 16; vtt++) {
            oa[vtt][0] *= f0; oa[vtt][1] *= f0;
            oa[vtt][2] *= f1; oa[vtt][3] *= f1;
        }

#pragma unroll
        for (int ks = 0; ks < 8; ks++) {
            uint32_t af[4];
            af[0] = pack2h(s[2 * ks][0],     s[2 * ks][1]);
            af[1] = pack2h(s[2 * ks][2],     s[2 * ks][3]);
            af[2] = pack2h(s[2 * ks + 1][0], s[2 * ks + 1][1]);
            af[3] = pack2h(s[2 * ks + 1][2], s[2 * ks + 1][3]);
            const int scol = ks * 16 + b_kc;
            const uint32_t vadd = stV + (scol >> 6) * 16384;
            const uint32_t sc2 = (scol & 63) * 2;
#pragma unroll
            for (int vt2 = 0; vt2 < 8; vt2++) {
                uint32_t bh[4];
                ldm_x4(bh, vadd + SW64((uint32_t)((vt2 * 16 + b_row) * 128) + sc2));
                mma_fp16(oa[2 * vt2],     af, bh);
                mma_fp16(oa[2 * vt2 + 1], af, bh + 2);
            }
        }
    }

    const float i0 = 1.f / l0, i1 = 1.f / l1;
    const int r0 = q0 + wid * 16 + (lane >> 2);
    HALF* op0 = out + (size_t)r0 * D + h * HD + (lane & 3) * 2;
    HALF* op1 = op0 + (size_t)8 * D;
#pragma unroll
    for (int vtt = 0; vtt < 16; vtt++) {
        *(uint32_t*)(op0 + vtt * 8) = pack2h(oa[vtt][0] * i0, oa[vtt][1] * i0);
        *(uint32_t*)(op1 + vtt * 8) = pack2h(oa[vtt][2] * i1, oa[vtt][3] * i1);
    }
}

// ---------------- cp.async pipelined GEMM (fp16, 1-pass, BK=64; R14 mainloop) ----------------
#define OUT_F32       0
#define OUT_F32RES    1
#define OUT_RELU_HI   4
#define OUT_HI        5

#define GSTAGE 32768
#define GEMM_SMEM (3 * GSTAGE)

template <int OUT>
__global__ void __launch_bounds__(256, 2)
tc_gemm(const uint16_t* __restrict__ Ah, int lda, long long sA,
        const uint16_t* __restrict__ Bh, int ldb, long long sB,
        const float* __restrict__ Res,
        float* __restrict__ Cf, uint16_t* __restrict__ Chi,
        int ldc, long long sC, int K, float alpha)
{
    extern __shared__ char smem[];
    const uint32_t sb = smem_u32(smem);
    const int tid = threadIdx.x, wid = tid >> 5, lane = tid & 31;
    const int z = blockIdx.z;
    Ah += (size_t)z * sA;
    Bh += (size_t)z * sB;
    const int m0 = blockIdx.x * 128;   // M fast-varying
    const int n0 = blockIdx.y * 128;
    const int wm = (wid & 3) * 32;
    const int wn = (wid >> 2) * 64;

    // loader (512B/warp window, conflict-free + coalesced)
    const int rowL = tid >> 2;
    const int cL   = tid & 3;
    const uint32_t o0 = SW64((uint32_t)(rowL * 64 + cL * 16));
    const uint32_t o1 = SW64((uint32_t)((rowL + 64) * 64 + cL * 16));
    const uint16_t* aht = Ah + (size_t)(m0 + rowL) * lda + cL * 8;
    const uint16_t* bht = Bh + (size_t)(n0 + rowL) * ldb + cL * 8;
    const size_t a64 = (size_t)64 * lda;
    const size_t b64 = (size_t)64 * ldb;

    auto issue = [&](int idx, int s) {
        const uint32_t st = sb + s * GSTAGE;
        const uint16_t* a1 = aht + idx * 64;
        const uint16_t* b1 = bht + idx * 64;
        CP16(st + o0,          a1);
        CP16(st + o1,          a1 + a64);
        CP16(st + 8192 + o0,   a1 + 32);
        CP16(st + 8192 + o1,   a1 + 32 + a64);
        CP16(st + 16384 + o0,  b1);
        CP16(st + 16384 + o1,  b1 + b64);
        CP16(st + 24576 + o0,  b1 + 32);
        CP16(st + 24576 + o1,  b1 + 32 + b64);
        CPCOMMIT();
    };

    float acc[2][8][4];
#pragma unroll
    for (int i = 0; i < 2; i++)
#pragma unroll
        for (int j = 0; j < 8; j++)
#pragma unroll
            for (int q = 0; q < 4; q++) acc[i][j][q] = 0.f;

    const int a_row = lane & 15;
    const int a_kc  = (lane >> 4) * 8;
    const int b_row = (lane & 7) + (lane >> 4) * 8;
    const int b_kc  = ((lane >> 3) & 1) * 8;

    const int nch = K >> 6;
    issue(0, 0);
    if (nch > 1) issue(1, 1);

    for (int i = 0; i < nch; i++) {
        if (i + 1 < nch) { CPWAIT1(); } else { CPWAIT0(); }
        __syncthreads();                       // single barrier per chunk
        if (i + 2 < nch) issue(i + 2, (i + 2) % 3);

        const uint32_t st  = sb + (i % 3) * GSTAGE;
#pragma unroll
        for (int ks = 0; ks < 4; ks++) {
            const uint32_t blk = (uint32_t)(ks >> 1) * 8192;
            const uint32_t akc2 = (uint32_t)(((ks & 1) * 16 + a_kc) * 2);
            const uint32_t bkc2 = (uint32_t)(((ks & 1) * 16 + b_kc) * 2);
            uint32_t ah[2][4];
#pragma unroll
            for (int mf = 0; mf < 2; mf++)
                ldm_x4(ah[mf], st + blk
                       + SW64((uint32_t)((wm + mf * 16 + a_row) * 64) + akc2));
#pragma unroll
            for (int p = 0; p < 4; p++) {
                uint32_t bh[4];
                ldm_x4(bh, st + 16384 + blk
                       + SW64((uint32_t)((wn + p * 16 + b_row) * 64) + bkc2));
#pragma unroll
                for (int mf = 0; mf < 2; mf++) {
                    mma_fp16(acc[mf][2 * p],     ah[mf], bh);
                    mma_fp16(acc[mf][2 * p + 1], ah[mf], bh + 2);
                }
            }
        }
    }

    const int r  = lane >> 2;
    const int c2 = (lane & 3) * 2;
#pragma unroll
    for (int mf = 0; mf < 2; mf++) {
#pragma unroll
        for (int hh = 0; hh < 2; hh++) {
            const int m = m0 + wm + mf * 16 + r + 8 * hh;
            const size_t rofs = (size_t)z * sC + (size_t)m * ldc + n0 + wn;
#pragma unroll
            for (int nf = 0; nf < 8; nf++) {
                float x0 = acc[mf][nf][2 * hh]     * alpha;
                float x1 = acc[mf][nf][2 * hh + 1] * alpha;
                const int nn = nf * 8 + c2;
                if (OUT == OUT_F32RES) {
                    const float2 rr = *(const float2*)(Res + (size_t)m * ldc + n0 + wn + nn);
                    x0 += rr.x; x1 += rr.y;
                } else if (OUT == OUT_RELU_HI) {
                    x0 = fmaxf(x0, 0.f); x1 = fmaxf(x1, 0.f);
                }
                if (OUT == OUT_F32 || OUT == OUT_F32RES) {
                    *(float2*)(Cf + rofs + nn) = make_float2(x0, x1);
                } else {
                    *(uint32_t*)(Chi + rofs + nn) = pack2h(x0, x1);
                }
            }
        }
    }
}

// ---------------- launch ----------------
extern "C" void kernel_launch(void* const* d_in, const int* in_sizes, int n_in,
                              void* d_out, int out_size)
{
    const int*   tokens = (const int*)d_in[0];
    const float* temb   = (const float*)d_in[1];
    const float* pemb   = (const float*)d_in[2];
    const float* wq     = (const float*)d_in[3];
    const float* wk     = (const float*)d_in[4];
    const float* wv     = (const float*)d_in[5];
    const float* wo     = (const float*)d_in[6];
    const float* wfi    = (const float*)d_in[7];
    const float* wfo    = (const float*)d_in[8];
    const float* ln1g   = (const float*)d_in[9];
    const float* ln1b   = (const float*)d_in[10];
    const float* ln2g   = (const float*)d_in[11];
    const float* ln2b   = (const float*)d_in[12];
    const float* lnfg   = (const float*)d_in[13];
    const float* lnfb   = (const float*)d_in[14];
    const float* wout   = (const float*)d_in[15];
    float*       out    = (float*)d_out;

    float *px, *px2, *px3;
    HALF *phh, *ph2h, *phfh, *paoh, *pffh, *pvth, *pqkvh;
    HALF *pwqkvTh, *pwoTh, *pwfiTh, *pwfoTh, *pwoutTh;
    cudaGetSymbolAddress((void**)&px,   g_x);
    cudaGetSymbolAddress((void**)&px2,  g_x2);
    cudaGetSymbolAddress((void**)&px3,  g_x3);
    cudaGetSymbolAddress((void**)&phh,  g_hh);
    cudaGetSymbolAddress((void**)&ph2h, g_h2h);
    cudaGetSymbolAddress((void**)&phfh, g_hfh);
    cudaGetSymbolAddress((void**)&paoh, g_aoh);
    cudaGetSymbolAddress((void**)&pffh, g_ffh);
    cudaGetSymbolAddress((void**)&pvth, g_vth);
    cudaGetSymbolAddress((void**)&pqkvh, g_qkvh);
    cudaGetSymbolAddress((void**)&pwqkvTh, g_wqkvTh);
    cudaGetSymbolAddress((void**)&pwoTh, g_woTh);
    cudaGetSymbolAddress((void**)&pwfiTh, g_wfiTh);
    cudaGetSymbolAddress((void**)&pwfoTh, g_wfoTh);
    cudaGetSymbolAddress((void**)&pwoutTh, g_woutTh);

    cudaFuncSetAttribute(tc_gemm<OUT_HI>,
                         cudaFuncAttributeMaxDynamicSharedMemorySize, GEMM_SMEM);
    cudaFuncSetAttribute(tc_gemm<OUT_F32RES>,
                         cudaFuncAttributeMaxDynamicSharedMemorySize, GEMM_SMEM);
    cudaFuncSetAttribute(tc_gemm<OUT_RELU_HI>,
                         cudaFuncAttributeMaxDynamicSharedMemorySize, GEMM_SMEM);
    cudaFuncSetAttribute(tc_gemm<OUT_F32>,
                         cudaFuncAttributeMaxDynamicSharedMemorySize, GEMM_SMEM);
    cudaFuncSetAttribute(flash_kernel,
                         cudaFuncAttributeMaxDynamicSharedMemorySize, FLASH_SMEM);

    // ---- side stream for weight conversions ----
    cudaStream_t s2;
    cudaStreamCreateWithFlags(&s2, cudaStreamNonBlocking);
    cudaEvent_t evFork, evWkv, evWo, evWfi, evWfo, evWout;
    cudaEventCreateWithFlags(&evFork, cudaEventDisableTiming);
    cudaEventCreateWithFlags(&evWkv,  cudaEventDisableTiming);
    cudaEventCreateWithFlags(&evWo,   cudaEventDisableTiming);
    cudaEventCreateWithFlags(&evWfi,  cudaEventDisableTiming);
    cudaEventCreateWithFlags(&evWfo,  cudaEventDisableTiming);
    cudaEventCreateWithFlags(&evWout, cudaEventDisableTiming);

    detect_tok_kernel<<<1, 256>>>(tokens);
    cudaEventRecord(evFork, 0);
    cudaStreamWaitEvent(s2, evFork, 0);

    // side stream: wk, wv first (wq runs on main stream in parallel)
    convT_kernel<<<dim3(D / 32, D / 64), 256, 0, s2>>>(wk, D, D, pwqkvTh + DD);
    convT_kernel<<<dim3(D / 32, D / 64), 256, 0, s2>>>(wv, D, D, pwqkvTh + 2 * DD);
    cudaEventRecord(evWkv, s2);
    convT_kernel<<<dim3(D / 32, D / 64), 256, 0, s2>>>(wo, D, D, pwoTh);
    cudaEventRecord(evWo, s2);
    convT_kernel<<<dim3(FF / 32, D / 64), 256, 0, s2>>>(wfi, D, FF, pwfiTh);
    cudaEventRecord(evWfi, s2);
    convT_kernel<<<dim3(D / 32, FF / 64), 256, 0, s2>>>(wfo, FF, D, pwfoTh);
    cudaEventRecord(evWfo, s2);
    convT_kernel<<<dim3(VOC / 32, D / 64), 256, 0, s2>>>(wout, D, VOC, pwoutTh);
    cudaEventRecord(evWout, s2);

    // main stream: wq conversion + fused embed+ln1 run concurrently w/ side stream
    convT_kernel<<<dim3(D / 32, D / 64), 256>>>(wq, D, D, pwqkvTh);
    embed_ln_kernel<<<S, 256>>>(tokens, temb, pemb, ln1g, ln1b, px, phh);
    cudaStreamWaitEvent(0, evWkv, 0);

    // attention: QKV 1-pass -> flash fused QK+softmax+PV
    tc_gemm<OUT_HI><<<dim3(S / 128, D / 128, 3), 256, GEMM_SMEM>>>(
        (uint16_t*)phh, D, 0, (uint16_t*)pwqkvTh, D, DD, nullptr,
        nullptr, (uint16_t*)pqkvh, D, SD, D, 1.f);
    vtrans_kernel<<<dim3(HD / 32, S / 32, H), 256>>>(pqkvh + 2 * SD, pvth);
    flash_kernel<<<dim3(S / 128, H), 256, FLASH_SMEM>>>(
        pqkvh, pqkvh + SD, pvth, paoh, 0.08838834764831845f);
    cudaStreamWaitEvent(0, evWo, 0);
    tc_gemm<OUT_F32RES><<<dim3(S / 128, D / 128, 1), 256, GEMM_SMEM>>>(
        (uint16_t*)paoh, D, 0, (uint16_t*)pwoTh, D, 0, px,
        px2, nullptr, D, 0, D, 1.f);

    // FFN block
    ln_kernel<<<S, 256>>>(px2, ln2g, ln2b, ph2h);
    cudaStreamWaitEvent(0, evWfi, 0);
    tc_gemm<OUT_RELU_HI><<<dim3(S / 128, FF / 128, 1), 256, GEMM_SMEM>>>(
        (uint16_t*)ph2h, D, 0, (uint16_t*)pwfiTh, D, 0, nullptr,
        nullptr, (uint16_t*)pffh, FF, 0, D, 1.f);
    cudaStreamWaitEvent(0, evWfo, 0);
    tc_gemm<OUT_F32RES><<<dim3(S / 128, D / 128, 1), 256, GEMM_SMEM>>>(
        (uint16_t*)pffh, FF, 0, (uint16_t*)pwfoTh, FF, 0, px2,
        px3, nullptr, D, 0, FF, 1.f);

    // final LN + logits
    ln_kernel<<<S, 256>>>(px3, lnfg, lnfb, phfh);
    cudaStreamWaitEvent(0, evWout, 0);
    tc_gemm<OUT_F32><<<dim3(S / 128, VOC / 128, 1), 256, GEMM_SMEM>>>(
        (uint16_t*)phfh, D, 0, (uint16_t*)pwoutTh, D, 0, nullptr,
        out, nullptr, VOC, 0, D, 1.f);
}